// round 15
// baseline (speedup 1.0000x reference)
#include <cuda_runtime.h>
#include <cuda_bf16.h>
#include <math.h>
#include <stdint.h>

// ---------------------------------------------------------------------------
// Problem constants
// ---------------------------------------------------------------------------
#define BATCH   4
#define SEQ     2048
#define DEMB    1024
#define NHEADS  16
#define DHEAD   64
#define MROWS   (BATCH * SEQ)        // 8192
#define QKV_N   (3 * DEMB)           // 3072

#define LOG2E 1.44269504088896f

// bf16 hi/lo scratch (device globals)
__device__ __nv_bfloat16 g_xhi[(size_t)MROWS * DEMB];
__device__ __nv_bfloat16 g_xlo[(size_t)MROWS * DEMB];
__device__ __nv_bfloat16 g_wihi[(size_t)QKV_N * DEMB];
__device__ __nv_bfloat16 g_wilo[(size_t)QKV_N * DEMB];
__device__ __nv_bfloat16 g_wohi[(size_t)DEMB * DEMB];
__device__ __nv_bfloat16 g_wolo[(size_t)DEMB * DEMB];
// head-major attention operands: [b][h][s][64]
__device__ __nv_bfloat16 g_qh[(size_t)MROWS * DEMB];
__device__ __nv_bfloat16 g_ql[(size_t)MROWS * DEMB];
__device__ __nv_bfloat16 g_kh[(size_t)MROWS * DEMB];
__device__ __nv_bfloat16 g_kl[(size_t)MROWS * DEMB];
__device__ __nv_bfloat16 g_vh[(size_t)MROWS * DEMB];
__device__ __nv_bfloat16 g_vl[(size_t)MROWS * DEMB];
// attention output, bf16 hi/lo, (B,S,D) row-major
__device__ __nv_bfloat16 g_ahi[(size_t)MROWS * DEMB];
__device__ __nv_bfloat16 g_alo[(size_t)MROWS * DEMB];

// ---------------------------------------------------------------------------
// PTX helpers (base sm_103-safe)
// ---------------------------------------------------------------------------
__device__ __forceinline__ uint32_t smem_u32(const void* p) {
    uint32_t a;
    asm("{ .reg .u64 t; cvta.to.shared.u64 t, %1; cvt.u32.u64 %0, t; }" : "=r"(a) : "l"(p));
    return a;
}
__device__ __forceinline__ void cp_async16(uint32_t saddr, const void* gaddr) {
    asm volatile("cp.async.ca.shared.global [%0], [%1], 16;" :: "r"(saddr), "l"(gaddr));
}
__device__ __forceinline__ void cp_commit() { asm volatile("cp.async.commit_group;"); }
template <int N>
__device__ __forceinline__ void cp_wait() { asm volatile("cp.async.wait_group %0;" :: "n"(N)); }

__device__ __forceinline__ void ldsm_x4(uint32_t addr, uint32_t& r0, uint32_t& r1,
                                        uint32_t& r2, uint32_t& r3) {
    asm volatile("ldmatrix.sync.aligned.m8n8.x4.shared.b16 {%0,%1,%2,%3}, [%4];"
                 : "=r"(r0), "=r"(r1), "=r"(r2), "=r"(r3) : "r"(addr));
}
__device__ __forceinline__ void ldsm_x4_t(uint32_t addr, uint32_t& r0, uint32_t& r1,
                                          uint32_t& r2, uint32_t& r3) {
    asm volatile("ldmatrix.sync.aligned.m8n8.x4.trans.shared.b16 {%0,%1,%2,%3}, [%4];"
                 : "=r"(r0), "=r"(r1), "=r"(r2), "=r"(r3) : "r"(addr));
}
__device__ __forceinline__ void mma_bf16(float* c, const uint32_t* a, uint32_t b0, uint32_t b1) {
    asm volatile(
        "mma.sync.aligned.m16n8k16.row.col.f32.bf16.bf16.f32 "
        "{%0,%1,%2,%3}, {%4,%5,%6,%7}, {%8,%9}, {%0,%1,%2,%3};"
        : "+f"(c[0]), "+f"(c[1]), "+f"(c[2]), "+f"(c[3])
        : "r"(a[0]), "r"(a[1]), "r"(a[2]), "r"(a[3]), "r"(b0), "r"(b1));
}
__device__ __forceinline__ float ex2(float x) {
    float r;
    asm("ex2.approx.f32 %0, %1;" : "=f"(r) : "f"(x));
    return r;
}
__device__ __forceinline__ uint32_t pack2(float x, float y) {
    __nv_bfloat162 t = __floats2bfloat162_rn(x, y);
    return *(uint32_t*)&t;
}
__device__ __forceinline__ void split2(float x, float y, uint32_t& hi, uint32_t& lo) {
    __nv_bfloat16 hx = __float2bfloat16(x);
    __nv_bfloat16 hy = __float2bfloat16(y);
    __nv_bfloat162 h2(hx, hy);
    hi = *(uint32_t*)&h2;
    lo = pack2(x - __bfloat162float(hx), y - __bfloat162float(hy));
}

// ---------------------------------------------------------------------------
// Fused fp32 -> bf16 hi/lo split of x, w_in, w_out — 2x ILP, 8 CTAs/SM
// ---------------------------------------------------------------------------
#define N4_X   ((MROWS * DEMB) / 4)
#define N4_WI  ((QKV_N * DEMB) / 4)
#define N4_WO  ((DEMB * DEMB) / 4)
#define N4_ALL (N4_X + N4_WI + N4_WO)

__device__ __forceinline__ void split_store4(const float4& v,
                                             __nv_bfloat16* hi, __nv_bfloat16* lo, int i)
{
    __nv_bfloat16 h0 = __float2bfloat16(v.x);
    __nv_bfloat16 h1 = __float2bfloat16(v.y);
    __nv_bfloat16 h2 = __float2bfloat16(v.z);
    __nv_bfloat16 h3 = __float2bfloat16(v.w);
    __nv_bfloat162* hp = (__nv_bfloat162*)(hi + (size_t)i * 4);
    __nv_bfloat162* lp = (__nv_bfloat162*)(lo + (size_t)i * 4);
    hp[0] = __nv_bfloat162(h0, h1); hp[1] = __nv_bfloat162(h2, h3);
    lp[0] = __nv_bfloat162(__float2bfloat16(v.x - __bfloat162float(h0)),
                           __float2bfloat16(v.y - __bfloat162float(h1)));
    lp[1] = __nv_bfloat162(__float2bfloat16(v.z - __bfloat162float(h2)),
                           __float2bfloat16(v.w - __bfloat162float(h3)));
}

__device__ __forceinline__ void split_route(int i, const float* __restrict__ x,
                                            const float* __restrict__ w_in,
                                            const float* __restrict__ w_out,
                                            __nv_bfloat16* xhi, __nv_bfloat16* xlo,
                                            __nv_bfloat16* wihi, __nv_bfloat16* wilo,
                                            __nv_bfloat16* wohi, __nv_bfloat16* wolo)
{
    if (i < N4_X) {
        split_store4(((const float4*)x)[i], xhi, xlo, i);
    } else if (i < N4_X + N4_WI) {
        int j = i - N4_X;
        split_store4(((const float4*)w_in)[j], wihi, wilo, j);
    } else {
        int j = i - N4_X - N4_WI;
        split_store4(((const float4*)w_out)[j], wohi, wolo, j);
    }
}

__global__ __launch_bounds__(256)
void split_all(const float* __restrict__ x, const float* __restrict__ w_in,
               const float* __restrict__ w_out,
               __nv_bfloat16* __restrict__ xhi, __nv_bfloat16* __restrict__ xlo,
               __nv_bfloat16* __restrict__ wihi, __nv_bfloat16* __restrict__ wilo,
               __nv_bfloat16* __restrict__ wohi, __nv_bfloat16* __restrict__ wolo)
{
    const int stride = gridDim.x * blockDim.x;
    int i = blockIdx.x * blockDim.x + threadIdx.x;
    for (; i + stride < N4_ALL; i += 2 * stride) {
        split_route(i,          x, w_in, w_out, xhi, xlo, wihi, wilo, wohi, wolo);
        split_route(i + stride, x, w_in, w_out, xhi, xlo, wihi, wilo, wohi, wolo);
    }
    if (i < N4_ALL)
        split_route(i, x, w_in, w_out, xhi, xlo, wihi, wilo, wohi, wolo);
}

// ---------------------------------------------------------------------------
// GEMM via mma.sync (3-pass hi/lo), pass-major MMA order, 2 CTAs/SM.
// (R8/R11-winning config: 128x128 tile, 80B padded rows, 2-stage pipeline.)
// MODE 0: C = acc + bias (fp32 out)
// MODE 1: QKV epilogue — split to bf16 hi/lo head-major [b][h][s][64]
//         (q pre-scaled by 0.125*log2(e) for the exp2 softmax)
// ---------------------------------------------------------------------------
#define BM 128
#define BN 128
#define BK 32
#define ROWB 80
#define TILE_SM (128 * ROWB)
#define STAGE_SM (4 * TILE_SM)
#define GEMM_SMEM (2 * STAGE_SM)

template <int MODE>
__global__ __launch_bounds__(256, 2)
void gemm_mma(const __nv_bfloat16* __restrict__ Ahi, const __nv_bfloat16* __restrict__ Alo,
              const __nv_bfloat16* __restrict__ Bhi, const __nv_bfloat16* __restrict__ Blo,
              const float* __restrict__ bias, float* __restrict__ C,
              __nv_bfloat16* __restrict__ qh, __nv_bfloat16* __restrict__ ql,
              __nv_bfloat16* __restrict__ kh, __nv_bfloat16* __restrict__ kl,
              __nv_bfloat16* __restrict__ vh, __nv_bfloat16* __restrict__ vl,
              int M, int N, int K)
{
    extern __shared__ char smem[];
    const uint32_t sbase = smem_u32(smem);
    const int tid = threadIdx.x;
    const int wid = tid >> 5;
    const int lid = tid & 31;
    const int warpM = wid & 3;
    const int warpN = wid >> 2;
    const int m0 = blockIdx.y * BM;
    const int n0 = blockIdx.x * BN;

    const int lr0 = tid >> 2;
    const int lq  = (tid & 3) * 16;

    const __nv_bfloat16* gsrc[4] = {
        Ahi + (size_t)m0 * K, Alo + (size_t)m0 * K,
        Bhi + (size_t)n0 * K, Blo + (size_t)n0 * K
    };

    float acc[2][8][4];
#pragma unroll
    for (int i = 0; i < 2; i++)
#pragma unroll
        for (int j = 0; j < 8; j++)
#pragma unroll
            for (int k = 0; k < 4; k++) acc[i][j][k] = 0.f;

    const int nch = K / BK;

    auto load_chunk = [&](int c, int buf) {
        const int k0 = c * BK;
        uint32_t st = sbase + buf * STAGE_SM;
#pragma unroll
        for (int t = 0; t < 4; t++) {
            const __nv_bfloat16* src = gsrc[t] + k0;
#pragma unroll
            for (int i = 0; i < 2; i++) {
                int r = lr0 + i * 64;
                cp_async16(st + t * TILE_SM + r * ROWB + lq,
                           (const char*)(src + (size_t)r * K) + lq);
            }
        }
        cp_commit();
    };

    auto compute_chunk = [&](int buf) {
        uint32_t st   = sbase + buf * STAGE_SM;
        uint32_t sAhi = st;
        uint32_t sAlo = st + TILE_SM;
        uint32_t sBhi = st + 2 * TILE_SM;
        uint32_t sBlo = st + 3 * TILE_SM;

#pragma unroll
        for (int ks = 0; ks < 2; ks++) {
            uint32_t ahi[2][4], alo[2][4];
            {
                int arow = warpM * 32 + (lid & 15);
                int acol = ks * 32 + (lid >> 4) * 16;
#pragma unroll
                for (int mt = 0; mt < 2; mt++) {
                    uint32_t off = (arow + mt * 16) * ROWB + acol;
                    ldsm_x4(sAhi + off, ahi[mt][0], ahi[mt][1], ahi[mt][2], ahi[mt][3]);
                    ldsm_x4(sAlo + off, alo[mt][0], alo[mt][1], alo[mt][2], alo[mt][3]);
                }
            }
            int brow_l = (lid >> 4) * 8 + (lid & 7);
            int bcol   = ks * 32 + ((lid >> 3) & 1) * 16;
#pragma unroll
            for (int nt = 0; nt < 4; nt++) {
                uint32_t off = (warpN * 64 + nt * 16 + brow_l) * ROWB + bcol;
                uint32_t bh[4], bl[4];
                ldsm_x4(sBhi + off, bh[0], bh[1], bh[2], bh[3]);
                ldsm_x4(sBlo + off, bl[0], bl[1], bl[2], bl[3]);
#pragma unroll
                for (int mt = 0; mt < 2; mt++)
#pragma unroll
                    for (int h = 0; h < 2; h++)
                        mma_bf16(acc[mt][nt * 2 + h], ahi[mt], bh[2 * h], bh[2 * h + 1]);
#pragma unroll
                for (int mt = 0; mt < 2; mt++)
#pragma unroll
                    for (int h = 0; h < 2; h++)
                        mma_bf16(acc[mt][nt * 2 + h], ahi[mt], bl[2 * h], bl[2 * h + 1]);
#pragma unroll
                for (int mt = 0; mt < 2; mt++)
#pragma unroll
                    for (int h = 0; h < 2; h++)
                        mma_bf16(acc[mt][nt * 2 + h], alo[mt], bh[2 * h], bh[2 * h + 1]);
            }
        }
    };

    load_chunk(0, 0);
    cp_wait<0>(); __syncthreads();
    for (int c = 0; c < nch; c++) {
        if (c + 1 < nch) load_chunk(c + 1, (c + 1) & 1);
        compute_chunk(c & 1);
        cp_wait<0>(); __syncthreads();
    }

    const int rbase = m0 + warpM * 32 + (lid >> 2);
    const int cbase = n0 + warpN * 64 + 2 * (lid & 3);

    if (MODE == 0) {
#pragma unroll
        for (int mt = 0; mt < 2; mt++) {
#pragma unroll
            for (int nt = 0; nt < 8; nt++) {
                int col = cbase + nt * 8;
                float b0 = __ldg(bias + col);
                float b1 = __ldg(bias + col + 1);
                int r0 = rbase + mt * 16;
                float2 v0 = make_float2(acc[mt][nt][0] + b0, acc[mt][nt][1] + b1);
                float2 v1 = make_float2(acc[mt][nt][2] + b0, acc[mt][nt][3] + b1);
                *(float2*)&C[(size_t)r0 * N + col]       = v0;
                *(float2*)&C[(size_t)(r0 + 8) * N + col] = v1;
            }
        }
    } else {
        const int t = n0 >> 10;
        const float qs = (t == 0) ? (0.125f * LOG2E) : 1.0f;
        __nv_bfloat16* dh = (t == 0) ? qh : (t == 1) ? kh : vh;
        __nv_bfloat16* dl = (t == 0) ? ql : (t == 1) ? kl : vl;
#pragma unroll
        for (int mt = 0; mt < 2; mt++) {
#pragma unroll
            for (int nt = 0; nt < 8; nt++) {
                int n  = cbase + nt * 8;
                float b0 = __ldg(bias + n);
                float b1 = __ldg(bias + n + 1);
                int nn = n & 1023;
                int hh = nn >> 6;
                int d  = nn & 63;
                int m  = rbase + mt * 16;
                int bb = m >> 11, ss = m & 2047;
                size_t idx = (((size_t)(bb * NHEADS + hh)) * SEQ + ss) * 64 + d;
                uint32_t hv, lv;
                split2((acc[mt][nt][0] + b0) * qs, (acc[mt][nt][1] + b1) * qs, hv, lv);
                *(uint32_t*)(dh + idx) = hv;
                *(uint32_t*)(dl + idx) = lv;
                int m2 = m + 8;
                bb = m2 >> 11; ss = m2 & 2047;
                idx = (((size_t)(bb * NHEADS + hh)) * SEQ + ss) * 64 + d;
                split2((acc[mt][nt][2] + b0) * qs, (acc[mt][nt][3] + b1) * qs, hv, lv);
                *(uint32_t*)(dh + idx) = hv;
                *(uint32_t*)(dl + idx) = lv;
            }
        }
    }
}

// ---------------------------------------------------------------------------
// Tensor-core flash attention (mma.sync, 3-pass hi/lo, FA2 fragment softmax).
// q-tile 128 (8 warps x 16 rows, 256 threads), k-tile 64, LPT order,
// exp2 softmax, dead-warp skip.
// R15: Q fragments hoisted to registers (loaded once); P fragments generated
// lazily inside the PV ks-loop (transient 8 regs instead of persistent 32).
// ---------------------------------------------------------------------------
#define AROWB 144
#define ATILE64 (64 * AROWB)
#define AQTILE  (128 * AROWB)
#define AQ_HI 0
#define AQ_LO AQTILE
#define ASTG  (2 * AQTILE)
#define ASTGSZ (4 * ATILE64)
#define ATT_SMEM (ASTG + 2 * ASTGSZ)   // 110592

__global__ __launch_bounds__(256, 2)
void attn_mma(const __nv_bfloat16* __restrict__ qh, const __nv_bfloat16* __restrict__ ql,
              const __nv_bfloat16* __restrict__ kh, const __nv_bfloat16* __restrict__ kl,
              const __nv_bfloat16* __restrict__ vh, const __nv_bfloat16* __restrict__ vl,
              __nv_bfloat16* __restrict__ ahi, __nv_bfloat16* __restrict__ alo,
              const int* __restrict__ causal_flag)
{
    extern __shared__ char smem[];
    const uint32_t sbase = smem_u32(smem);
    const int tid = threadIdx.x;
    const int wid = tid >> 5;
    const int lid = tid & 31;
    const int iq  = (int)gridDim.x - 1 - (int)blockIdx.x;   // LPT
    const int bh  = blockIdx.y;
    const int q0  = iq * 128;
    const int causal = *causal_flag;

    const size_t headbase = (size_t)bh * SEQ * 64;

    auto load_tile64 = [&](uint32_t sdst, const __nv_bfloat16* g) {
        int row = tid >> 2;
        uint32_t sr = sbase + sdst + row * AROWB + (tid & 3) * 32;
        const char* gr = (const char*)(g + (size_t)row * 64) + (tid & 3) * 32;
        cp_async16(sr, gr);
        cp_async16(sr + 16, gr + 16);
    };

    load_tile64(AQ_HI,           qh + headbase + (size_t)q0 * 64);
    load_tile64(AQ_HI + ATILE64, qh + headbase + (size_t)(q0 + 64) * 64);
    load_tile64(AQ_LO,           ql + headbase + (size_t)q0 * 64);
    load_tile64(AQ_LO + ATILE64, ql + headbase + (size_t)(q0 + 64) * 64);

    auto load_kv = [&](int jk, int buf) {
        size_t off = headbase + (size_t)jk * 64 * 64;
        uint32_t st = ASTG + buf * ASTGSZ;
        load_tile64(st,               kh + off);
        load_tile64(st + ATILE64,     kl + off);
        load_tile64(st + 2 * ATILE64, vh + off);
        load_tile64(st + 3 * ATILE64, vl + off);
        cp_commit();
    };

    load_kv(0, 0);
    cp_wait<0>(); __syncthreads();

    // Q fragments hoisted: loaded ONCE per CTA (saves 8 ldsm_x4 per k-tile)
    const int arow = wid * 16 + (lid & 15);
    const int acol = (lid >> 4) * 16;
    uint32_t qfh[4][4], qfl[4][4];
#pragma unroll
    for (int ks = 0; ks < 4; ks++) {
        uint32_t qoff = arow * AROWB + ks * 32 + acol;
        ldsm_x4(sbase + AQ_HI + qoff, qfh[ks][0], qfh[ks][1], qfh[ks][2], qfh[ks][3]);
        ldsm_x4(sbase + AQ_LO + qoff, qfl[ks][0], qfl[ks][1], qfl[ks][2], qfl[ks][3]);
    }

    float Oacc[8][4];
#pragma unroll
    for (int j = 0; j < 8; j++)
#pragma unroll
        for (int c = 0; c < 4; c++) Oacc[j][c] = 0.f;
    float m0 = -INFINITY, m1 = -INFINITY, l0 = 0.f, l1 = 0.f;

    const int ntiles = causal ? (2 * iq + 2) : (SEQ / 64);

    for (int jk = 0; jk < ntiles; jk++) {
        if (jk + 1 < ntiles) load_kv(jk + 1, (jk + 1) & 1);

        uint32_t st = sbase + ASTG + (jk & 1) * ASTGSZ;
        uint32_t sKh = st, sKl = st + ATILE64, sVh = st + 2 * ATILE64, sVl = st + 3 * ATILE64;

        const bool active = !(causal && (jk == ntiles - 1) && wid < 4);

        float S[8][4];
#pragma unroll
        for (int j = 0; j < 8; j++)
#pragma unroll
            for (int c = 0; c < 4; c++) S[j][c] = active ? 0.f : -INFINITY;

        if (active) {
            int brow = (lid >> 4) * 8 + (lid & 7);
            int bcx  = ((lid >> 3) & 1) * 16;
#pragma unroll
            for (int ks = 0; ks < 4; ks++) {
#pragma unroll
                for (int nt = 0; nt < 4; nt += 2) {
                    uint32_t off0 = (nt * 16 + brow) * AROWB + ks * 32 + bcx;
                    uint32_t off1 = ((nt + 1) * 16 + brow) * AROWB + ks * 32 + bcx;
                    uint32_t bh0[4], bl0[4], bh1[4], bl1[4];
                    ldsm_x4(sKh + off0, bh0[0], bh0[1], bh0[2], bh0[3]);
                    ldsm_x4(sKl + off0, bl0[0], bl0[1], bl0[2], bl0[3]);
                    ldsm_x4(sKh + off1, bh1[0], bh1[1], bh1[2], bh1[3]);
                    ldsm_x4(sKl + off1, bl1[0], bl1[1], bl1[2], bl1[3]);
#pragma unroll
                    for (int h = 0; h < 2; h++) {
                        mma_bf16(S[nt * 2 + h],       qfh[ks], bh0[2 * h], bh0[2 * h + 1]);
                        mma_bf16(S[(nt + 1) * 2 + h], qfh[ks], bh1[2 * h], bh1[2 * h + 1]);
                    }
#pragma unroll
                    for (int h = 0; h < 2; h++) {
                        mma_bf16(S[nt * 2 + h],       qfh[ks], bl0[2 * h], bl0[2 * h + 1]);
                        mma_bf16(S[(nt + 1) * 2 + h], qfh[ks], bl1[2 * h], bl1[2 * h + 1]);
                    }
#pragma unroll
                    for (int h = 0; h < 2; h++) {
                        mma_bf16(S[nt * 2 + h],       qfl[ks], bh0[2 * h], bh0[2 * h + 1]);
                        mma_bf16(S[(nt + 1) * 2 + h], qfl[ks], bh1[2 * h], bh1[2 * h + 1]);
                    }
                }
            }
        }

        const int k0 = jk * 64;
        if (causal && jk >= 2 * iq && active) {
            int rg0 = q0 + wid * 16 + (lid >> 2);
#pragma unroll
            for (int j = 0; j < 8; j++) {
                int cg = k0 + j * 8 + 2 * (lid & 3);
#pragma unroll
                for (int c = 0; c < 4; c++) {
                    int rg = rg0 + (c >> 1) * 8;
                    if (cg + (c & 1) > rg) S[j][c] = -INFINITY;
                }
            }
        }

        float mx0 = -INFINITY, mx1 = -INFINITY;
#pragma unroll
        for (int j = 0; j < 8; j++) {
            mx0 = fmaxf(mx0, fmaxf(S[j][0], S[j][1]));
            mx1 = fmaxf(mx1, fmaxf(S[j][2], S[j][3]));
        }
        mx0 = fmaxf(mx0, __shfl_xor_sync(0xffffffff, mx0, 1));
        mx0 = fmaxf(mx0, __shfl_xor_sync(0xffffffff, mx0, 2));
        mx1 = fmaxf(mx1, __shfl_xor_sync(0xffffffff, mx1, 1));
        mx1 = fmaxf(mx1, __shfl_xor_sync(0xffffffff, mx1, 2));

        float mn0 = fmaxf(m0, mx0), mn1 = fmaxf(m1, mx1);
        float sc0 = ex2(m0 - mn0), sc1 = ex2(m1 - mn1);

#pragma unroll
        for (int j = 0; j < 8; j++) {
            Oacc[j][0] *= sc0; Oacc[j][1] *= sc0;
            Oacc[j][2] *= sc1; Oacc[j][3] *= sc1;
        }

        // ---- fused P-generation + PV (P fragments transient per ks) ----
        float sum0 = 0.f, sum1 = 0.f;
        if (active) {
            int vr  = ((lid >> 3) & 1) * 8 + (lid & 7);
            int vcx = (lid >> 4) * 16;
#pragma unroll
            for (int ks = 0; ks < 4; ks++) {
                uint32_t ph[4], pl[4];
#pragma unroll
                for (int half = 0; half < 2; half++) {
                    int j = 2 * ks + half;
                    float p0 = ex2(S[j][0] - mn0);
                    float p1 = ex2(S[j][1] - mn0);
                    float p2 = ex2(S[j][2] - mn1);
                    float p3 = ex2(S[j][3] - mn1);
                    sum0 += p0 + p1;
                    sum1 += p2 + p3;
                    split2(p0, p1, ph[half * 2 + 0], pl[half * 2 + 0]);
                    split2(p2, p3, ph[half * 2 + 1], pl[half * 2 + 1]);
                }
#pragma unroll
                for (int nt = 0; nt < 4; nt += 2) {
                    uint32_t off0 = (ks * 16 + vr) * AROWB + nt * 32 + vcx;
                    uint32_t off1 = (ks * 16 + vr) * AROWB + (nt + 1) * 32 + vcx;
                    uint32_t vh0[4], vl0[4], vh1[4], vl1[4];
                    ldsm_x4_t(sVh + off0, vh0[0], vh0[1], vh0[2], vh0[3]);
                    ldsm_x4_t(sVl + off0, vl0[0], vl0[1], vl0[2], vl0[3]);
                    ldsm_x4_t(sVh + off1, vh1[0], vh1[1], vh1[2], vh1[3]);
                    ldsm_x4_t(sVl + off1, vl1[0], vl1[1], vl1[2], vl1[3]);
#pragma unroll
                    for (int h = 0; h < 2; h++) {
                        mma_bf16(Oacc[nt * 2 + h],       ph, vh0[2 * h], vh0[2 * h + 1]);
                        mma_bf16(Oacc[(nt + 1) * 2 + h], ph, vh1[2 * h], vh1[2 * h + 1]);
                    }
#pragma unroll
                    for (int h = 0; h < 2; h++) {
                        mma_bf16(Oacc[nt * 2 + h],       ph, vl0[2 * h], vl0[2 * h + 1]);
                        mma_bf16(Oacc[(nt + 1) * 2 + h], ph, vl1[2 * h], vl1[2 * h + 1]);
                    }
#pragma unroll
                    for (int h = 0; h < 2; h++) {
                        mma_bf16(Oacc[nt * 2 + h],       pl, vh0[2 * h], vh0[2 * h + 1]);
                        mma_bf16(Oacc[(nt + 1) * 2 + h], pl, vh1[2 * h], vh1[2 * h + 1]);
                    }
                }
            }
        }
        sum0 += __shfl_xor_sync(0xffffffff, sum0, 1);
        sum0 += __shfl_xor_sync(0xffffffff, sum0, 2);
        sum1 += __shfl_xor_sync(0xffffffff, sum1, 1);
        sum1 += __shfl_xor_sync(0xffffffff, sum1, 2);

        l0 = l0 * sc0 + sum0;
        l1 = l1 * sc1 + sum1;
        m0 = mn0; m1 = mn1;

        cp_wait<0>(); __syncthreads();
    }

    // ---- epilogue: fused fp32->bf16 hi/lo split ----
    const int b = bh >> 4, h = bh & 15;
    const int row0 = q0 + wid * 16 + (lid >> 2);
    float inv0 = 1.f / l0, inv1 = 1.f / l1;
#pragma unroll
    for (int j = 0; j < 8; j++) {
        int col = h * 64 + j * 8 + 2 * (lid & 3);
        size_t idx0 = (size_t)(b * SEQ + row0) * DEMB + col;
        size_t idx1 = (size_t)(b * SEQ + row0 + 8) * DEMB + col;
        uint32_t hv, lv;
        split2(Oacc[j][0] * inv0, Oacc[j][1] * inv0, hv, lv);
        *(uint32_t*)(ahi + idx0) = hv;
        *(uint32_t*)(alo + idx0) = lv;
        split2(Oacc[j][2] * inv1, Oacc[j][3] * inv1, hv, lv);
        *(uint32_t*)(ahi + idx1) = hv;
        *(uint32_t*)(alo + idx1) = lv;
    }
}

// ---------------------------------------------------------------------------
// Launch
// ---------------------------------------------------------------------------
extern "C" void kernel_launch(void* const* d_in, const int* in_sizes, int n_in,
                              void* d_out, int out_size)
{
    (void)in_sizes; (void)n_in; (void)out_size;
    const float* x      = (const float*)d_in[0];
    const float* w_in   = (const float*)d_in[1];
    const float* b_in   = (const float*)d_in[2];
    const float* w_out  = (const float*)d_in[3];
    const float* b_out  = (const float*)d_in[4];
    const int*   causal = (const int*)  d_in[5];
    float* out = (float*)d_out;

    __nv_bfloat16 *xhi, *xlo, *wihi, *wilo, *wohi, *wolo;
    __nv_bfloat16 *qh, *ql, *kh, *kl, *vh, *vl, *ahi, *alo;
    cudaGetSymbolAddress((void**)&xhi, g_xhi);
    cudaGetSymbolAddress((void**)&xlo, g_xlo);
    cudaGetSymbolAddress((void**)&wihi, g_wihi);
    cudaGetSymbolAddress((void**)&wilo, g_wilo);
    cudaGetSymbolAddress((void**)&wohi, g_wohi);
    cudaGetSymbolAddress((void**)&wolo, g_wolo);
    cudaGetSymbolAddress((void**)&qh, g_qh);
    cudaGetSymbolAddress((void**)&ql, g_ql);
    cudaGetSymbolAddress((void**)&kh, g_kh);
    cudaGetSymbolAddress((void**)&kl, g_kl);
    cudaGetSymbolAddress((void**)&vh, g_vh);
    cudaGetSymbolAddress((void**)&vl, g_vl);
    cudaGetSymbolAddress((void**)&ahi, g_ahi);
    cudaGetSymbolAddress((void**)&alo, g_alo);

    cudaFuncSetAttribute(gemm_mma<0>, cudaFuncAttributeMaxDynamicSharedMemorySize, GEMM_SMEM);
    cudaFuncSetAttribute(gemm_mma<1>, cudaFuncAttributeMaxDynamicSharedMemorySize, GEMM_SMEM);
    cudaFuncSetAttribute(attn_mma, cudaFuncAttributeMaxDynamicSharedMemorySize, ATT_SMEM);

    // 1) fused split of x, w_in, w_out (2x ILP)
    split_all<<<2368, 256>>>(x, w_in, w_out, xhi, xlo, wihi, wilo, wohi, wolo);

    // 2) QKV projection (128x128, 2 CTAs/SM), fused head-major hi/lo split
    {
        dim3 grid(QKV_N / BN, MROWS / BM);   // (24, 64)
        gemm_mma<1><<<grid, 256, GEMM_SMEM>>>(xhi, xlo, wihi, wilo, b_in, nullptr,
                                              qh, ql, kh, kl, vh, vl,
                                              MROWS, QKV_N, DEMB);
    }

    // 3) attention (q-tile 128, LPT, exp2 softmax, hoisted Q, lazy P)
    {
        dim3 grid(SEQ / 128, BATCH * NHEADS);
        attn_mma<<<grid, 256, ATT_SMEM>>>(qh, ql, kh, kl, vh, vl, ahi, alo, causal);
    }

    // 4) output projection (128x128, 2 CTAs/SM, fp32 + bias)
    {
        dim3 grid(DEMB / BN, MROWS / BM);    // (8, 64)
        gemm_mma<0><<<grid, 256, GEMM_SMEM>>>(ahi, alo, wohi, wolo, b_out, out,
                                              nullptr, nullptr, nullptr, nullptr, nullptr, nullptr,
                                              MROWS, DEMB, DEMB);
    }
}

// round 16
// speedup vs baseline: 1.0230x; 1.0230x over previous
#include <cuda_runtime.h>
#include <cuda_bf16.h>
#include <math.h>
#include <stdint.h>

// ---------------------------------------------------------------------------
// Problem constants
// ---------------------------------------------------------------------------
#define BATCH   4
#define SEQ     2048
#define DEMB    1024
#define NHEADS  16
#define DHEAD   64
#define MROWS   (BATCH * SEQ)        // 8192
#define QKV_N   (3 * DEMB)           // 3072

#define LOG2E 1.44269504088896f

// bf16 hi/lo scratch (device globals)
__device__ __nv_bfloat16 g_xhi[(size_t)MROWS * DEMB];
__device__ __nv_bfloat16 g_xlo[(size_t)MROWS * DEMB];
__device__ __nv_bfloat16 g_wihi[(size_t)QKV_N * DEMB];
__device__ __nv_bfloat16 g_wilo[(size_t)QKV_N * DEMB];
__device__ __nv_bfloat16 g_wohi[(size_t)DEMB * DEMB];
__device__ __nv_bfloat16 g_wolo[(size_t)DEMB * DEMB];
// head-major attention operands: [b][h][s][64]
__device__ __nv_bfloat16 g_qh[(size_t)MROWS * DEMB];
__device__ __nv_bfloat16 g_ql[(size_t)MROWS * DEMB];
__device__ __nv_bfloat16 g_kh[(size_t)MROWS * DEMB];
__device__ __nv_bfloat16 g_kl[(size_t)MROWS * DEMB];
__device__ __nv_bfloat16 g_vh[(size_t)MROWS * DEMB];
__device__ __nv_bfloat16 g_vl[(size_t)MROWS * DEMB];
// attention output, bf16 hi/lo, (B,S,D) row-major
__device__ __nv_bfloat16 g_ahi[(size_t)MROWS * DEMB];
__device__ __nv_bfloat16 g_alo[(size_t)MROWS * DEMB];

// ---------------------------------------------------------------------------
// PTX helpers (base sm_103-safe)
// ---------------------------------------------------------------------------
__device__ __forceinline__ uint32_t smem_u32(const void* p) {
    uint32_t a;
    asm("{ .reg .u64 t; cvta.to.shared.u64 t, %1; cvt.u32.u64 %0, t; }" : "=r"(a) : "l"(p));
    return a;
}
__device__ __forceinline__ void cp_async16(uint32_t saddr, const void* gaddr) {
    asm volatile("cp.async.ca.shared.global [%0], [%1], 16;" :: "r"(saddr), "l"(gaddr));
}
__device__ __forceinline__ void cp_commit() { asm volatile("cp.async.commit_group;"); }
template <int N>
__device__ __forceinline__ void cp_wait() { asm volatile("cp.async.wait_group %0;" :: "n"(N)); }

__device__ __forceinline__ void ldsm_x4(uint32_t addr, uint32_t& r0, uint32_t& r1,
                                        uint32_t& r2, uint32_t& r3) {
    asm volatile("ldmatrix.sync.aligned.m8n8.x4.shared.b16 {%0,%1,%2,%3}, [%4];"
                 : "=r"(r0), "=r"(r1), "=r"(r2), "=r"(r3) : "r"(addr));
}
__device__ __forceinline__ void ldsm_x4_t(uint32_t addr, uint32_t& r0, uint32_t& r1,
                                          uint32_t& r2, uint32_t& r3) {
    asm volatile("ldmatrix.sync.aligned.m8n8.x4.trans.shared.b16 {%0,%1,%2,%3}, [%4];"
                 : "=r"(r0), "=r"(r1), "=r"(r2), "=r"(r3) : "r"(addr));
}
__device__ __forceinline__ void mma_bf16(float* c, const uint32_t* a, uint32_t b0, uint32_t b1) {
    asm volatile(
        "mma.sync.aligned.m16n8k16.row.col.f32.bf16.bf16.f32 "
        "{%0,%1,%2,%3}, {%4,%5,%6,%7}, {%8,%9}, {%0,%1,%2,%3};"
        : "+f"(c[0]), "+f"(c[1]), "+f"(c[2]), "+f"(c[3])
        : "r"(a[0]), "r"(a[1]), "r"(a[2]), "r"(a[3]), "r"(b0), "r"(b1));
}
__device__ __forceinline__ float ex2(float x) {
    float r;
    asm("ex2.approx.f32 %0, %1;" : "=f"(r) : "f"(x));
    return r;
}
__device__ __forceinline__ uint32_t pack2(float x, float y) {
    __nv_bfloat162 t = __floats2bfloat162_rn(x, y);
    return *(uint32_t*)&t;
}
__device__ __forceinline__ void split2(float x, float y, uint32_t& hi, uint32_t& lo) {
    __nv_bfloat16 hx = __float2bfloat16(x);
    __nv_bfloat16 hy = __float2bfloat16(y);
    __nv_bfloat162 h2(hx, hy);
    hi = *(uint32_t*)&h2;
    lo = pack2(x - __bfloat162float(hx), y - __bfloat162float(hy));
}

// ---------------------------------------------------------------------------
// Fused fp32 -> bf16 hi/lo split of x, w_in, w_out — 2x ILP
// ---------------------------------------------------------------------------
#define N4_X   ((MROWS * DEMB) / 4)
#define N4_WI  ((QKV_N * DEMB) / 4)
#define N4_WO  ((DEMB * DEMB) / 4)
#define N4_ALL (N4_X + N4_WI + N4_WO)

__device__ __forceinline__ void split_store4(const float4& v,
                                             __nv_bfloat16* hi, __nv_bfloat16* lo, int i)
{
    __nv_bfloat16 h0 = __float2bfloat16(v.x);
    __nv_bfloat16 h1 = __float2bfloat16(v.y);
    __nv_bfloat16 h2 = __float2bfloat16(v.z);
    __nv_bfloat16 h3 = __float2bfloat16(v.w);
    __nv_bfloat162* hp = (__nv_bfloat162*)(hi + (size_t)i * 4);
    __nv_bfloat162* lp = (__nv_bfloat162*)(lo + (size_t)i * 4);
    hp[0] = __nv_bfloat162(h0, h1); hp[1] = __nv_bfloat162(h2, h3);
    lp[0] = __nv_bfloat162(__float2bfloat16(v.x - __bfloat162float(h0)),
                           __float2bfloat16(v.y - __bfloat162float(h1)));
    lp[1] = __nv_bfloat162(__float2bfloat16(v.z - __bfloat162float(h2)),
                           __float2bfloat16(v.w - __bfloat162float(h3)));
}

__device__ __forceinline__ void split_route(int i, const float* __restrict__ x,
                                            const float* __restrict__ w_in,
                                            const float* __restrict__ w_out,
                                            __nv_bfloat16* xhi, __nv_bfloat16* xlo,
                                            __nv_bfloat16* wihi, __nv_bfloat16* wilo,
                                            __nv_bfloat16* wohi, __nv_bfloat16* wolo)
{
    if (i < N4_X) {
        split_store4(((const float4*)x)[i], xhi, xlo, i);
    } else if (i < N4_X + N4_WI) {
        int j = i - N4_X;
        split_store4(((const float4*)w_in)[j], wihi, wilo, j);
    } else {
        int j = i - N4_X - N4_WI;
        split_store4(((const float4*)w_out)[j], wohi, wolo, j);
    }
}

__global__ __launch_bounds__(256)
void split_all(const float* __restrict__ x, const float* __restrict__ w_in,
               const float* __restrict__ w_out,
               __nv_bfloat16* __restrict__ xhi, __nv_bfloat16* __restrict__ xlo,
               __nv_bfloat16* __restrict__ wihi, __nv_bfloat16* __restrict__ wilo,
               __nv_bfloat16* __restrict__ wohi, __nv_bfloat16* __restrict__ wolo)
{
    const int stride = gridDim.x * blockDim.x;
    int i = blockIdx.x * blockDim.x + threadIdx.x;
    for (; i + stride < N4_ALL; i += 2 * stride) {
        split_route(i,          x, w_in, w_out, xhi, xlo, wihi, wilo, wohi, wolo);
        split_route(i + stride, x, w_in, w_out, xhi, xlo, wihi, wilo, wohi, wolo);
    }
    if (i < N4_ALL)
        split_route(i, x, w_in, w_out, xhi, xlo, wihi, wilo, wohi, wolo);
}

// ---------------------------------------------------------------------------
// GEMM via mma.sync (3-pass hi/lo), pass-major MMA order, 2 CTAs/SM.
// (R8/R11-winning config.) MODE 0: fp32 out + bias. MODE 1: QKV epilogue.
// ---------------------------------------------------------------------------
#define BM 128
#define BN 128
#define BK 32
#define ROWB 80
#define TILE_SM (128 * ROWB)
#define STAGE_SM (4 * TILE_SM)
#define GEMM_SMEM (2 * STAGE_SM)

template <int MODE>
__global__ __launch_bounds__(256, 2)
void gemm_mma(const __nv_bfloat16* __restrict__ Ahi, const __nv_bfloat16* __restrict__ Alo,
              const __nv_bfloat16* __restrict__ Bhi, const __nv_bfloat16* __restrict__ Blo,
              const float* __restrict__ bias, float* __restrict__ C,
              __nv_bfloat16* __restrict__ qh, __nv_bfloat16* __restrict__ ql,
              __nv_bfloat16* __restrict__ kh, __nv_bfloat16* __restrict__ kl,
              __nv_bfloat16* __restrict__ vh, __nv_bfloat16* __restrict__ vl,
              int M, int N, int K)
{
    extern __shared__ char smem[];
    const uint32_t sbase = smem_u32(smem);
    const int tid = threadIdx.x;
    const int wid = tid >> 5;
    const int lid = tid & 31;
    const int warpM = wid & 3;
    const int warpN = wid >> 2;
    const int m0 = blockIdx.y * BM;
    const int n0 = blockIdx.x * BN;

    const int lr0 = tid >> 2;
    const int lq  = (tid & 3) * 16;

    const __nv_bfloat16* gsrc[4] = {
        Ahi + (size_t)m0 * K, Alo + (size_t)m0 * K,
        Bhi + (size_t)n0 * K, Blo + (size_t)n0 * K
    };

    float acc[2][8][4];
#pragma unroll
    for (int i = 0; i < 2; i++)
#pragma unroll
        for (int j = 0; j < 8; j++)
#pragma unroll
            for (int k = 0; k < 4; k++) acc[i][j][k] = 0.f;

    const int nch = K / BK;

    auto load_chunk = [&](int c, int buf) {
        const int k0 = c * BK;
        uint32_t st = sbase + buf * STAGE_SM;
#pragma unroll
        for (int t = 0; t < 4; t++) {
            const __nv_bfloat16* src = gsrc[t] + k0;
#pragma unroll
            for (int i = 0; i < 2; i++) {
                int r = lr0 + i * 64;
                cp_async16(st + t * TILE_SM + r * ROWB + lq,
                           (const char*)(src + (size_t)r * K) + lq);
            }
        }
        cp_commit();
    };

    auto compute_chunk = [&](int buf) {
        uint32_t st   = sbase + buf * STAGE_SM;
        uint32_t sAhi = st;
        uint32_t sAlo = st + TILE_SM;
        uint32_t sBhi = st + 2 * TILE_SM;
        uint32_t sBlo = st + 3 * TILE_SM;

#pragma unroll
        for (int ks = 0; ks < 2; ks++) {
            uint32_t ahi[2][4], alo[2][4];
            {
                int arow = warpM * 32 + (lid & 15);
                int acol = ks * 32 + (lid >> 4) * 16;
#pragma unroll
                for (int mt = 0; mt < 2; mt++) {
                    uint32_t off = (arow + mt * 16) * ROWB + acol;
                    ldsm_x4(sAhi + off, ahi[mt][0], ahi[mt][1], ahi[mt][2], ahi[mt][3]);
                    ldsm_x4(sAlo + off, alo[mt][0], alo[mt][1], alo[mt][2], alo[mt][3]);
                }
            }
            int brow_l = (lid >> 4) * 8 + (lid & 7);
            int bcol   = ks * 32 + ((lid >> 3) & 1) * 16;
#pragma unroll
            for (int nt = 0; nt < 4; nt++) {
                uint32_t off = (warpN * 64 + nt * 16 + brow_l) * ROWB + bcol;
                uint32_t bh[4], bl[4];
                ldsm_x4(sBhi + off, bh[0], bh[1], bh[2], bh[3]);
                ldsm_x4(sBlo + off, bl[0], bl[1], bl[2], bl[3]);
#pragma unroll
                for (int mt = 0; mt < 2; mt++)
#pragma unroll
                    for (int h = 0; h < 2; h++)
                        mma_bf16(acc[mt][nt * 2 + h], ahi[mt], bh[2 * h], bh[2 * h + 1]);
#pragma unroll
                for (int mt = 0; mt < 2; mt++)
#pragma unroll
                    for (int h = 0; h < 2; h++)
                        mma_bf16(acc[mt][nt * 2 + h], ahi[mt], bl[2 * h], bl[2 * h + 1]);
#pragma unroll
                for (int mt = 0; mt < 2; mt++)
#pragma unroll
                    for (int h = 0; h < 2; h++)
                        mma_bf16(acc[mt][nt * 2 + h], alo[mt], bh[2 * h], bh[2 * h + 1]);
            }
        }
    };

    load_chunk(0, 0);
    cp_wait<0>(); __syncthreads();
    for (int c = 0; c < nch; c++) {
        if (c + 1 < nch) load_chunk(c + 1, (c + 1) & 1);
        compute_chunk(c & 1);
        cp_wait<0>(); __syncthreads();
    }

    const int rbase = m0 + warpM * 32 + (lid >> 2);
    const int cbase = n0 + warpN * 64 + 2 * (lid & 3);

    if (MODE == 0) {
#pragma unroll
        for (int mt = 0; mt < 2; mt++) {
#pragma unroll
            for (int nt = 0; nt < 8; nt++) {
                int col = cbase + nt * 8;
                float b0 = __ldg(bias + col);
                float b1 = __ldg(bias + col + 1);
                int r0 = rbase + mt * 16;
                float2 v0 = make_float2(acc[mt][nt][0] + b0, acc[mt][nt][1] + b1);
                float2 v1 = make_float2(acc[mt][nt][2] + b0, acc[mt][nt][3] + b1);
                *(float2*)&C[(size_t)r0 * N + col]       = v0;
                *(float2*)&C[(size_t)(r0 + 8) * N + col] = v1;
            }
        }
    } else {
        const int t = n0 >> 10;
        const float qs = (t == 0) ? (0.125f * LOG2E) : 1.0f;
        __nv_bfloat16* dh = (t == 0) ? qh : (t == 1) ? kh : vh;
        __nv_bfloat16* dl = (t == 0) ? ql : (t == 1) ? kl : vl;
#pragma unroll
        for (int mt = 0; mt < 2; mt++) {
#pragma unroll
            for (int nt = 0; nt < 8; nt++) {
                int n  = cbase + nt * 8;
                float b0 = __ldg(bias + n);
                float b1 = __ldg(bias + n + 1);
                int nn = n & 1023;
                int hh = nn >> 6;
                int d  = nn & 63;
                int m  = rbase + mt * 16;
                int bb = m >> 11, ss = m & 2047;
                size_t idx = (((size_t)(bb * NHEADS + hh)) * SEQ + ss) * 64 + d;
                uint32_t hv, lv;
                split2((acc[mt][nt][0] + b0) * qs, (acc[mt][nt][1] + b1) * qs, hv, lv);
                *(uint32_t*)(dh + idx) = hv;
                *(uint32_t*)(dl + idx) = lv;
                int m2 = m + 8;
                bb = m2 >> 11; ss = m2 & 2047;
                idx = (((size_t)(bb * NHEADS + hh)) * SEQ + ss) * 64 + d;
                split2((acc[mt][nt][2] + b0) * qs, (acc[mt][nt][3] + b1) * qs, hv, lv);
                *(uint32_t*)(dh + idx) = hv;
                *(uint32_t*)(dl + idx) = lv;
            }
        }
    }
}

// ---------------------------------------------------------------------------
// Tensor-core flash attention (R14 structure: persistent P, batched exp2).
// R16 single change: qfh hoisted to registers (16 regs, loaded once);
// qfl still reloaded from smem per ks.
// ---------------------------------------------------------------------------
#define AROWB 144
#define ATILE64 (64 * AROWB)
#define AQTILE  (128 * AROWB)
#define AQ_HI 0
#define AQ_LO AQTILE
#define ASTG  (2 * AQTILE)
#define ASTGSZ (4 * ATILE64)
#define ATT_SMEM (ASTG + 2 * ASTGSZ)   // 110592

__global__ __launch_bounds__(256, 2)
void attn_mma(const __nv_bfloat16* __restrict__ qh, const __nv_bfloat16* __restrict__ ql,
              const __nv_bfloat16* __restrict__ kh, const __nv_bfloat16* __restrict__ kl,
              const __nv_bfloat16* __restrict__ vh, const __nv_bfloat16* __restrict__ vl,
              __nv_bfloat16* __restrict__ ahi, __nv_bfloat16* __restrict__ alo,
              const int* __restrict__ causal_flag)
{
    extern __shared__ char smem[];
    const uint32_t sbase = smem_u32(smem);
    const int tid = threadIdx.x;
    const int wid = tid >> 5;
    const int lid = tid & 31;
    const int iq  = (int)gridDim.x - 1 - (int)blockIdx.x;   // LPT
    const int bh  = blockIdx.y;
    const int q0  = iq * 128;
    const int causal = *causal_flag;

    const size_t headbase = (size_t)bh * SEQ * 64;

    auto load_tile64 = [&](uint32_t sdst, const __nv_bfloat16* g) {
        int row = tid >> 2;
        uint32_t sr = sbase + sdst + row * AROWB + (tid & 3) * 32;
        const char* gr = (const char*)(g + (size_t)row * 64) + (tid & 3) * 32;
        cp_async16(sr, gr);
        cp_async16(sr + 16, gr + 16);
    };

    load_tile64(AQ_HI,           qh + headbase + (size_t)q0 * 64);
    load_tile64(AQ_HI + ATILE64, qh + headbase + (size_t)(q0 + 64) * 64);
    load_tile64(AQ_LO,           ql + headbase + (size_t)q0 * 64);
    load_tile64(AQ_LO + ATILE64, ql + headbase + (size_t)(q0 + 64) * 64);

    auto load_kv = [&](int jk, int buf) {
        size_t off = headbase + (size_t)jk * 64 * 64;
        uint32_t st = ASTG + buf * ASTGSZ;
        load_tile64(st,               kh + off);
        load_tile64(st + ATILE64,     kl + off);
        load_tile64(st + 2 * ATILE64, vh + off);
        load_tile64(st + 3 * ATILE64, vl + off);
        cp_commit();
    };

    load_kv(0, 0);
    cp_wait<0>(); __syncthreads();

    // Partial Q hoist: qfh resident in registers (16 regs), qfl stays in smem
    const int arow = wid * 16 + (lid & 15);
    const int acol = (lid >> 4) * 16;
    uint32_t qfh[4][4];
#pragma unroll
    for (int ks = 0; ks < 4; ks++) {
        uint32_t qoff = arow * AROWB + ks * 32 + acol;
        ldsm_x4(sbase + AQ_HI + qoff, qfh[ks][0], qfh[ks][1], qfh[ks][2], qfh[ks][3]);
    }

    float Oacc[8][4];
#pragma unroll
    for (int j = 0; j < 8; j++)
#pragma unroll
        for (int c = 0; c < 4; c++) Oacc[j][c] = 0.f;
    float m0 = -INFINITY, m1 = -INFINITY, l0 = 0.f, l1 = 0.f;

    const int ntiles = causal ? (2 * iq + 2) : (SEQ / 64);

    for (int jk = 0; jk < ntiles; jk++) {
        if (jk + 1 < ntiles) load_kv(jk + 1, (jk + 1) & 1);

        uint32_t st = sbase + ASTG + (jk & 1) * ASTGSZ;
        uint32_t sKh = st, sKl = st + ATILE64, sVh = st + 2 * ATILE64, sVl = st + 3 * ATILE64;

        const bool active = !(causal && (jk == ntiles - 1) && wid < 4);

        float S[8][4];
#pragma unroll
        for (int j = 0; j < 8; j++)
#pragma unroll
            for (int c = 0; c < 4; c++) S[j][c] = active ? 0.f : -INFINITY;

        if (active) {
            int brow = (lid >> 4) * 8 + (lid & 7);
            int bcx  = ((lid >> 3) & 1) * 16;
#pragma unroll
            for (int ks = 0; ks < 4; ks++) {
                uint32_t qfl_[4];
                ldsm_x4(sbase + AQ_LO + arow * AROWB + ks * 32 + acol,
                        qfl_[0], qfl_[1], qfl_[2], qfl_[3]);
#pragma unroll
                for (int nt = 0; nt < 4; nt += 2) {
                    uint32_t off0 = (nt * 16 + brow) * AROWB + ks * 32 + bcx;
                    uint32_t off1 = ((nt + 1) * 16 + brow) * AROWB + ks * 32 + bcx;
                    uint32_t bh0[4], bl0[4], bh1[4], bl1[4];
                    ldsm_x4(sKh + off0, bh0[0], bh0[1], bh0[2], bh0[3]);
                    ldsm_x4(sKl + off0, bl0[0], bl0[1], bl0[2], bl0[3]);
                    ldsm_x4(sKh + off1, bh1[0], bh1[1], bh1[2], bh1[3]);
                    ldsm_x4(sKl + off1, bl1[0], bl1[1], bl1[2], bl1[3]);
#pragma unroll
                    for (int h = 0; h < 2; h++) {
                        mma_bf16(S[nt * 2 + h],       qfh[ks], bh0[2 * h], bh0[2 * h + 1]);
                        mma_bf16(S[(nt + 1) * 2 + h], qfh[ks], bh1[2 * h], bh1[2 * h + 1]);
                    }
#pragma unroll
                    for (int h = 0; h < 2; h++) {
                        mma_bf16(S[nt * 2 + h],       qfh[ks], bl0[2 * h], bl0[2 * h + 1]);
                        mma_bf16(S[(nt + 1) * 2 + h], qfh[ks], bl1[2 * h], bl1[2 * h + 1]);
                    }
#pragma unroll
                    for (int h = 0; h < 2; h++) {
                        mma_bf16(S[nt * 2 + h],       qfl_, bh0[2 * h], bh0[2 * h + 1]);
                        mma_bf16(S[(nt + 1) * 2 + h], qfl_, bh1[2 * h], bh1[2 * h + 1]);
                    }
                }
            }
        }

        const int k0 = jk * 64;
        if (causal && jk >= 2 * iq && active) {
            int rg0 = q0 + wid * 16 + (lid >> 2);
#pragma unroll
            for (int j = 0; j < 8; j++) {
                int cg = k0 + j * 8 + 2 * (lid & 3);
#pragma unroll
                for (int c = 0; c < 4; c++) {
                    int rg = rg0 + (c >> 1) * 8;
                    if (cg + (c & 1) > rg) S[j][c] = -INFINITY;
                }
            }
        }

        float mx0 = -INFINITY, mx1 = -INFINITY;
#pragma unroll
        for (int j = 0; j < 8; j++) {
            mx0 = fmaxf(mx0, fmaxf(S[j][0], S[j][1]));
            mx1 = fmaxf(mx1, fmaxf(S[j][2], S[j][3]));
        }
        mx0 = fmaxf(mx0, __shfl_xor_sync(0xffffffff, mx0, 1));
        mx0 = fmaxf(mx0, __shfl_xor_sync(0xffffffff, mx0, 2));
        mx1 = fmaxf(mx1, __shfl_xor_sync(0xffffffff, mx1, 1));
        mx1 = fmaxf(mx1, __shfl_xor_sync(0xffffffff, mx1, 2));

        float mn0 = fmaxf(m0, mx0), mn1 = fmaxf(m1, mx1);
        float sc0 = ex2(m0 - mn0), sc1 = ex2(m1 - mn1);

        uint32_t pfh[4][4], pfl[4][4];
        float sum0 = 0.f, sum1 = 0.f;
#pragma unroll
        for (int ks = 0; ks < 4; ks++) {
#pragma unroll
            for (int half = 0; half < 2; half++) {
                int j = 2 * ks + half;
                float p0 = ex2(S[j][0] - mn0);
                float p1 = ex2(S[j][1] - mn0);
                float p2 = ex2(S[j][2] - mn1);
                float p3 = ex2(S[j][3] - mn1);
                sum0 += p0 + p1;
                sum1 += p2 + p3;
                split2(p0, p1, pfh[ks][half * 2 + 0], pfl[ks][half * 2 + 0]);
                split2(p2, p3, pfh[ks][half * 2 + 1], pfl[ks][half * 2 + 1]);
            }
        }
        sum0 += __shfl_xor_sync(0xffffffff, sum0, 1);
        sum0 += __shfl_xor_sync(0xffffffff, sum0, 2);
        sum1 += __shfl_xor_sync(0xffffffff, sum1, 1);
        sum1 += __shfl_xor_sync(0xffffffff, sum1, 2);

        l0 = l0 * sc0 + sum0;
        l1 = l1 * sc1 + sum1;
        m0 = mn0; m1 = mn1;

#pragma unroll
        for (int j = 0; j < 8; j++) {
            Oacc[j][0] *= sc0; Oacc[j][1] *= sc0;
            Oacc[j][2] *= sc1; Oacc[j][3] *= sc1;
        }

        if (active) {
            int vr  = ((lid >> 3) & 1) * 8 + (lid & 7);
            int vcx = (lid >> 4) * 16;
#pragma unroll
            for (int ks = 0; ks < 4; ks++) {
#pragma unroll
                for (int nt = 0; nt < 4; nt += 2) {
                    uint32_t off0 = (ks * 16 + vr) * AROWB + nt * 32 + vcx;
                    uint32_t off1 = (ks * 16 + vr) * AROWB + (nt + 1) * 32 + vcx;
                    uint32_t vh0[4], vl0[4], vh1[4], vl1[4];
                    ldsm_x4_t(sVh + off0, vh0[0], vh0[1], vh0[2], vh0[3]);
                    ldsm_x4_t(sVl + off0, vl0[0], vl0[1], vl0[2], vl0[3]);
                    ldsm_x4_t(sVh + off1, vh1[0], vh1[1], vh1[2], vh1[3]);
                    ldsm_x4_t(sVl + off1, vl1[0], vl1[1], vl1[2], vl1[3]);
#pragma unroll
                    for (int h = 0; h < 2; h++) {
                        mma_bf16(Oacc[nt * 2 + h],       pfh[ks], vh0[2 * h], vh0[2 * h + 1]);
                        mma_bf16(Oacc[(nt + 1) * 2 + h], pfh[ks], vh1[2 * h], vh1[2 * h + 1]);
                    }
#pragma unroll
                    for (int h = 0; h < 2; h++) {
                        mma_bf16(Oacc[nt * 2 + h],       pfh[ks], vl0[2 * h], vl0[2 * h + 1]);
                        mma_bf16(Oacc[(nt + 1) * 2 + h], pfh[ks], vl1[2 * h], vl1[2 * h + 1]);
                    }
#pragma unroll
                    for (int h = 0; h < 2; h++) {
                        mma_bf16(Oacc[nt * 2 + h],       pfl[ks], vh0[2 * h], vh0[2 * h + 1]);
                        mma_bf16(Oacc[(nt + 1) * 2 + h], pfl[ks], vh1[2 * h], vh1[2 * h + 1]);
                    }
                }
            }
        }
        cp_wait<0>(); __syncthreads();
    }

    // ---- epilogue: fused fp32->bf16 hi/lo split ----
    const int b = bh >> 4, h = bh & 15;
    const int row0 = q0 + wid * 16 + (lid >> 2);
    float inv0 = 1.f / l0, inv1 = 1.f / l1;
#pragma unroll
    for (int j = 0; j < 8; j++) {
        int col = h * 64 + j * 8 + 2 * (lid & 3);
        size_t idx0 = (size_t)(b * SEQ + row0) * DEMB + col;
        size_t idx1 = (size_t)(b * SEQ + row0 + 8) * DEMB + col;
        uint32_t hv, lv;
        split2(Oacc[j][0] * inv0, Oacc[j][1] * inv0, hv, lv);
        *(uint32_t*)(ahi + idx0) = hv;
        *(uint32_t*)(alo + idx0) = lv;
        split2(Oacc[j][2] * inv1, Oacc[j][3] * inv1, hv, lv);
        *(uint32_t*)(ahi + idx1) = hv;
        *(uint32_t*)(alo + idx1) = lv;
    }
}

// ---------------------------------------------------------------------------
// Launch
// ---------------------------------------------------------------------------
extern "C" void kernel_launch(void* const* d_in, const int* in_sizes, int n_in,
                              void* d_out, int out_size)
{
    (void)in_sizes; (void)n_in; (void)out_size;
    const float* x      = (const float*)d_in[0];
    const float* w_in   = (const float*)d_in[1];
    const float* b_in   = (const float*)d_in[2];
    const float* w_out  = (const float*)d_in[3];
    const float* b_out  = (const float*)d_in[4];
    const int*   causal = (const int*)  d_in[5];
    float* out = (float*)d_out;

    __nv_bfloat16 *xhi, *xlo, *wihi, *wilo, *wohi, *wolo;
    __nv_bfloat16 *qh, *ql, *kh, *kl, *vh, *vl, *ahi, *alo;
    cudaGetSymbolAddress((void**)&xhi, g_xhi);
    cudaGetSymbolAddress((void**)&xlo, g_xlo);
    cudaGetSymbolAddress((void**)&wihi, g_wihi);
    cudaGetSymbolAddress((void**)&wilo, g_wilo);
    cudaGetSymbolAddress((void**)&wohi, g_wohi);
    cudaGetSymbolAddress((void**)&wolo, g_wolo);
    cudaGetSymbolAddress((void**)&qh, g_qh);
    cudaGetSymbolAddress((void**)&ql, g_ql);
    cudaGetSymbolAddress((void**)&kh, g_kh);
    cudaGetSymbolAddress((void**)&kl, g_kl);
    cudaGetSymbolAddress((void**)&vh, g_vh);
    cudaGetSymbolAddress((void**)&vl, g_vl);
    cudaGetSymbolAddress((void**)&ahi, g_ahi);
    cudaGetSymbolAddress((void**)&alo, g_alo);

    cudaFuncSetAttribute(gemm_mma<0>, cudaFuncAttributeMaxDynamicSharedMemorySize, GEMM_SMEM);
    cudaFuncSetAttribute(gemm_mma<1>, cudaFuncAttributeMaxDynamicSharedMemorySize, GEMM_SMEM);
    cudaFuncSetAttribute(attn_mma, cudaFuncAttributeMaxDynamicSharedMemorySize, ATT_SMEM);

    // 1) fused split of x, w_in, w_out (2x ILP)
    split_all<<<2368, 256>>>(x, w_in, w_out, xhi, xlo, wihi, wilo, wohi, wolo);

    // 2) QKV projection (128x128, 2 CTAs/SM), fused head-major hi/lo split
    {
        dim3 grid(QKV_N / BN, MROWS / BM);   // (24, 64)
        gemm_mma<1><<<grid, 256, GEMM_SMEM>>>(xhi, xlo, wihi, wilo, b_in, nullptr,
                                              qh, ql, kh, kl, vh, vl,
                                              MROWS, QKV_N, DEMB);
    }

    // 3) attention (q-tile 128, LPT, exp2, dead-warp skip, partial Q-hoist)
    {
        dim3 grid(SEQ / 128, BATCH * NHEADS);
        attn_mma<<<grid, 256, ATT_SMEM>>>(qh, ql, kh, kl, vh, vl, ahi, alo, causal);
    }

    // 4) output projection (128x128, 2 CTAs/SM, fp32 + bias)
    {
        dim3 grid(DEMB / BN, MROWS / BM);    // (8, 64)
        gemm_mma<0><<<grid, 256, GEMM_SMEM>>>(ahi, alo, wohi, wolo, b_out, out,
                                              nullptr, nullptr, nullptr, nullptr, nullptr, nullptr,
                                              MROWS, DEMB, DEMB);
    }
}